// round 11
// baseline (speedup 1.0000x reference)
#include <cuda_runtime.h>
#include <cuda_bf16.h>
#include <cstdint>

#define Bn 1024
#define Hn 256
#define Gn 768
#define On 512
#define Tn 60
#define Cc 15
#define MAXG 18
#define OT (On*Tn)

__device__ __align__(16) uint32_t g_Bw[120 * 2 * 12288];
__device__ __align__(16) uint32_t g_Bo[120 * 2 * 8192];
__device__ __align__(16) uint32_t g_Bx[120 * 2 * 12288];
__device__ __align__(16) uint32_t g_h[2 * MAXG * 2 * 16384];
__device__ int g_perm[Bn], g_gcam[MAXG], g_goff[MAXG], g_gcnt[MAXG], g_ngrp, g_bar[MAXG];

__device__ __forceinline__ float sigf(float v) { return 1.f / (1.f + __expf(-v)); }
__device__ __forceinline__ float tanhf_(float v) { return 2.f * sigf(2.f * v) - 1.f; }
__device__ __forceinline__ void bfsplit2(float f0, float f1, uint32_t& hi, uint32_t& lo) {
    unsigned short a = __bfloat16_as_ushort(__float2bfloat16_rn(f0));
    unsigned short b = __bfloat16_as_ushort(__float2bfloat16_rn(f1));
    float r0 = f0 - __uint_as_float((uint32_t)a << 16);
    float r1 = f1 - __uint_as_float((uint32_t)b << 16);
    unsigned short c = __bfloat16_as_ushort(__float2bfloat16_rn(r0));
    unsigned short d = __bfloat16_as_ushort(__float2bfloat16_rn(r1));
    hi = (uint32_t)a | ((uint32_t)b << 16);
    lo = (uint32_t)c | ((uint32_t)d << 16);
}
__device__ __forceinline__ void mma4(float* c, const uint32_t* a, uint32_t b0, uint32_t b1) {
    asm volatile("mma.sync.aligned.m16n8k16.row.col.f32.bf16.bf16.f32 "
                 "{%0,%1,%2,%3},{%4,%5,%6,%7},{%8,%9},{%0,%1,%2,%3};"
                 : "+f"(c[0]), "+f"(c[1]), "+f"(c[2]), "+f"(c[3])
                 : "r"(a[0]), "r"(a[1]), "r"(a[2]), "r"(a[3]), "r"(b0), "r"(b1));
}
__device__ __forceinline__ void ldfrag(const uint32_t* hb, int w0, int r0, int r1,
                                       uint32_t* ah, uint32_t* al) {
    ah[0] = hb[r0 * 128 + w0];         ah[1] = hb[r1 * 128 + w0];
    ah[2] = hb[r0 * 128 + w0 + 4];     ah[3] = hb[r1 * 128 + w0 + 4];
    al[0] = hb[16384 + r0 * 128 + w0]; al[1] = hb[16384 + r1 * 128 + w0];
    al[2] = hb[16384 + r0 * 128 + w0 + 4]; al[3] = hb[16384 + r1 * 128 + w0 + 4];
}

// ---------------------------------------------------------------------------
__global__ void prep(const int* __restrict__ cam, const float* __restrict__ Wi,
                     const float* __restrict__ Wh, const float* __restrict__ Wc) {
    if (blockIdx.x == 0) {
        __shared__ int cn[Cc], cu[Cc], co[Cc];
        int tid = threadIdx.x;
        if (tid < Cc) cn[tid] = 0;
        if (tid < MAXG) g_bar[tid] = 0;
        __syncthreads();
        for (int b = tid; b < Bn; b += blockDim.x) atomicAdd(&cn[cam[b]], 1);
        __syncthreads();
        if (tid == 0) {
            int o = 0;
            for (int c = 0; c < Cc; c++) { co[c] = o; cu[c] = o; o += cn[c]; }
            int g = 0;
            for (int c = 0; c < Cc; c++)
                for (int s = 0; s < cn[c] && g < MAXG; s += 128) {
                    g_gcam[g] = c; g_goff[g] = co[c] + s; g_gcnt[g] = min(128, cn[c] - s); g++;
                }
            g_ngrp = g;
        }
        __syncthreads();
        for (int b = tid; b < Bn; b += blockDim.x) { int p = atomicAdd(&cu[cam[b]], 1); g_perm[p] = b; }
    }
    int idx = blockIdx.x * blockDim.x + threadIdx.x, st = gridDim.x * blockDim.x;
    const int NWG = 120 * 12 * 512;
    for (int i = idx; i < NWG; i += st) {
        int lane = i & 31, kc = (i >> 5) & 15, T = (i >> 9) % 12, tile = i / (512 * 12);
        int c = tile >> 3, j = tile & 7;
        size_t row = (size_t)c * Gn + (T >> 2) * 256 + 32 * j + 8 * (T & 3) + (lane >> 2);
        int k0 = 16 * kc + (lane & 3) * 2;
        size_t o = (size_t)tile * 24576 + (size_t)((T * 16 + kc) * 32 + lane) * 2;
        uint32_t h0, l0, h1, l1;
        const float* w = Wh + row * Hn;
        bfsplit2(w[k0], w[k0 + 1], h0, l0); bfsplit2(w[k0 + 8], w[k0 + 9], h1, l1);
        g_Bw[o] = h0; g_Bw[o + 1] = h1; g_Bw[o + 12288] = l0; g_Bw[o + 12289] = l1;
        w = Wi + row * Hn;
        bfsplit2(w[k0], w[k0 + 1], h0, l0); bfsplit2(w[k0 + 8], w[k0 + 9], h1, l1);
        g_Bx[o] = h0; g_Bx[o + 1] = h1; g_Bx[o + 12288] = l0; g_Bx[o + 12289] = l1;
    }
    const int NWO = 120 * 8 * 512;
    for (int i = idx; i < NWO; i += st) {
        int lane = i & 31, kc = (i >> 5) & 15, T = (i >> 9) & 7, tile = i / (512 * 8);
        int c = tile >> 3, j = tile & 7;
        const float* w = Wc + ((size_t)c * On + 64 * j + 8 * T + (lane >> 2)) * Hn;
        int k0 = 16 * kc + (lane & 3) * 2;
        size_t o = (size_t)tile * 16384 + (size_t)((T * 16 + kc) * 32 + lane) * 2;
        uint32_t h0, l0, h1, l1;
        bfsplit2(w[k0], w[k0 + 1], h0, l0); bfsplit2(w[k0 + 8], w[k0 + 9], h1, l1);
        g_Bo[o] = h0; g_Bo[o + 1] = h1; g_Bo[o + 8192] = l0; g_Bo[o + 8193] = l1;
    }
}

// ---------------------------------------------------------------------------
// 144 CTAs x 384 threads. Warps 0-7: gate GEMM+epilogue (m-tile = wid).
// Warps 8-11: out GEMM (m-tiles 2*(wid-8), 2*(wid-8)+1), pipelined t = i-1.
// ---------------------------------------------------------------------------
__global__ void __launch_bounds__(384, 1)
gru(const float* __restrict__ x, const float* __restrict__ b_ih,
    const float* __restrict__ b_hh, const float* __restrict__ bc,
    float* __restrict__ out) {
    extern __shared__ __align__(16) uint32_t sm[];
    uint32_t* sB  = sm;                 // 24576 u32
    uint32_t* sBo = sm + 24576;         // 16384 u32
    float* bcs = (float*)(sm + 40960);  // 64
    float* bhs = (float*)(sm + 41024);  // 32
    int* samp  = (int*)(sm + 41056);    // 128

    const int grp = blockIdx.x >> 3, j = blockIdx.x & 7;
    if (grp >= g_ngrp) return;
    const int cam = g_gcam[grp], off = g_goff[grp], cnt = g_gcnt[grp];
    const int tile = cam * 8 + j;
    const int tid = threadIdx.x, wid = tid >> 5, lane = tid & 31;
    const int qr = lane >> 2, qc = lane & 3;
    const bool isG = wid < 8;

    if (tid < 128) samp[tid] = (tid < cnt) ? g_perm[off + tid] : 0;
    if (tid < 64) bcs[tid] = bc[cam * On + 64 * j + tid];
    if (tid < 32) bhs[tid] = b_hh[cam * Gn + 512 + 32 * j + tid];
    {
        const uint4* s = (const uint4*)(g_Bw + (size_t)tile * 24576);
        uint4* d = (uint4*)sB;
        for (int i = tid; i < 6144; i += 384) d[i] = s[i];
        const uint4* s2 = (const uint4*)(g_Bo + (size_t)tile * 16384);
        uint4* d2 = (uint4*)sBo;
        for (int i = tid; i < 4096; i += 384) d2[i] = s2[i];
    }
    __syncthreads();

    // per-role setup
    const int mt  = isG ? wid : 0;
    const int mA  = isG ? 0 : 2 * (wid - 8), mB = mA + 1;
    const bool actg = isG && (16 * mt) < cnt;
    const bool actA = !isG && (16 * mA) < cnt;
    const bool actB = !isG && (16 * mB) < cnt;
    const int r0g = 16 * mt + qr, r1g = r0g + 8;
    const int r0A = 16 * mA + qr, r1A = r0A + 8;
    const int r0B = 16 * mB + qr, r1B = r0B + 8;

    float gi[48], hold[16];
    if (actg) {  // gi = x@Wi + biases -> registers
#pragma unroll
        for (int q = 0; q < 48; q++) gi[q] = 0.f;
        const uint32_t* bx = g_Bx + (size_t)tile * 24576;
        const float* x0 = (r0g < cnt) ? x + (size_t)samp[r0g] * Hn : 0;
        const float* x1 = (r1g < cnt) ? x + (size_t)samp[r1g] * Hn : 0;
        for (int kc = 0; kc < 16; kc++) {
            int k0 = 16 * kc + qc * 2;
            float2 p00 = x0 ? *(const float2*)(x0 + k0) : make_float2(0.f, 0.f);
            float2 p02 = x0 ? *(const float2*)(x0 + k0 + 8) : make_float2(0.f, 0.f);
            float2 p10 = x1 ? *(const float2*)(x1 + k0) : make_float2(0.f, 0.f);
            float2 p12 = x1 ? *(const float2*)(x1 + k0 + 8) : make_float2(0.f, 0.f);
            uint32_t ah[4], al[4];
            bfsplit2(p00.x, p00.y, ah[0], al[0]);
            bfsplit2(p10.x, p10.y, ah[1], al[1]);
            bfsplit2(p02.x, p02.y, ah[2], al[2]);
            bfsplit2(p12.x, p12.y, ah[3], al[3]);
#pragma unroll
            for (int T = 0; T < 12; T++) {
                size_t o = (size_t)((T * 16 + kc) * 32 + lane) * 2;
                uint2 bh = *(const uint2*)(bx + o);
                uint2 bl = *(const uint2*)(bx + 12288 + o);
                mma4(gi + 4 * T, ah, bh.x, bh.y);
                mma4(gi + 4 * T, ah, bl.x, bl.y);
                mma4(gi + 4 * T, al, bh.x, bh.y);
            }
        }
#pragma unroll
        for (int T = 0; T < 12; T++) {
            int g = T >> 2;
            int col = g * 256 + 32 * j + 8 * (T & 3) + qc * 2;
            float b0 = b_ih[cam * Gn + col], b1 = b_ih[cam * Gn + col + 1];
            if (g < 2) { b0 += b_hh[cam * Gn + col]; b1 += b_hh[cam * Gn + col + 1]; }
            gi[4 * T] += b0; gi[4 * T + 1] += b1; gi[4 * T + 2] += b0; gi[4 * T + 3] += b1;
        }
    }
#pragma unroll
    for (int q = 0; q < 16; q++) hold[q] = 0.f;
    int bt = 0;

    for (int i = 0; i <= Tn; i++) {
        if (actg && i < Tn) {  // ---- gate path ----
            float gacc[48];
#pragma unroll
            for (int q = 0; q < 48; q++) gacc[q] = 0.f;
            if (i > 0) {
                const uint32_t* hb = g_h + (size_t)((i & 1) * MAXG + grp) * 2 * 16384;
                uint32_t ah[4], al[4], nh[4], nl[4];
                ldfrag(hb, qc, r0g, r1g, ah, al);
#pragma unroll 4
                for (int kc = 0; kc < 16; kc++) {
                    if (kc < 15) ldfrag(hb, qc + 8 * (kc + 1), r0g, r1g, nh, nl);
#pragma unroll
                    for (int T = 0; T < 12; T++) {
                        size_t o = (size_t)((T * 16 + kc) * 32 + lane) * 2;
                        uint2 bh = *(const uint2*)(sB + o);
                        uint2 bl = *(const uint2*)(sB + 12288 + o);
                        mma4(gacc + 4 * T, ah, bh.x, bh.y);
                        mma4(gacc + 4 * T, ah, bl.x, bl.y);
                        mma4(gacc + 4 * T, al, bh.x, bh.y);
                    }
#pragma unroll
                    for (int q = 0; q < 4; q++) { ah[q] = nh[q]; al[q] = nl[q]; }
                }
            }
            uint32_t* dh = g_h + (size_t)(((i + 1) & 1) * MAXG + grp) * 2 * 16384;
#pragma unroll
            for (int tt = 0; tt < 4; tt++) {
                int cb = 8 * tt + qc * 2;
                float bn0 = bhs[cb], bn1 = bhs[cb + 1];
                float h0, h1, h2, h3;
                { float r = sigf(gi[4 * tt] + gacc[4 * tt]);
                  float z = sigf(gi[16 + 4 * tt] + gacc[16 + 4 * tt]);
                  float n = tanhf_(gi[32 + 4 * tt] + r * (gacc[32 + 4 * tt] + bn0));
                  h0 = (1.f - z) * n + z * hold[4 * tt]; hold[4 * tt] = h0; }
                { float r = sigf(gi[4 * tt + 1] + gacc[4 * tt + 1]);
                  float z = sigf(gi[16 + 4 * tt + 1] + gacc[16 + 4 * tt + 1]);
                  float n = tanhf_(gi[32 + 4 * tt + 1] + r * (gacc[32 + 4 * tt + 1] + bn1));
                  h1 = (1.f - z) * n + z * hold[4 * tt + 1]; hold[4 * tt + 1] = h1; }
                { float r = sigf(gi[4 * tt + 2] + gacc[4 * tt + 2]);
                  float z = sigf(gi[16 + 4 * tt + 2] + gacc[16 + 4 * tt + 2]);
                  float n = tanhf_(gi[32 + 4 * tt + 2] + r * (gacc[32 + 4 * tt + 2] + bn0));
                  h2 = (1.f - z) * n + z * hold[4 * tt + 2]; hold[4 * tt + 2] = h2; }
                { float r = sigf(gi[4 * tt + 3] + gacc[4 * tt + 3]);
                  float z = sigf(gi[16 + 4 * tt + 3] + gacc[16 + 4 * tt + 3]);
                  float n = tanhf_(gi[32 + 4 * tt + 3] + r * (gacc[32 + 4 * tt + 3] + bn1));
                  h3 = (1.f - z) * n + z * hold[4 * tt + 3]; hold[4 * tt + 3] = h3; }
                uint32_t w0h, w0l, w1h, w1l;
                bfsplit2(h0, h1, w0h, w0l);
                bfsplit2(h2, h3, w1h, w1l);
                int wrd = 16 * j + 4 * tt + qc;
                dh[r0g * 128 + wrd] = w0h; dh[r1g * 128 + wrd] = w1h;
                dh[16384 + r0g * 128 + wrd] = w0l; dh[16384 + r1g * 128 + wrd] = w1l;
            }
        } else if (!isG && i > 0 && (actA || actB)) {  // ---- out path ----
            float oA[32], oB[32];
#pragma unroll
            for (int q = 0; q < 32; q++) { oA[q] = 0.f; oB[q] = 0.f; }
            const uint32_t* hb = g_h + (size_t)((i & 1) * MAXG + grp) * 2 * 16384;
            uint32_t aA[4], lA[4], aB[4], lB[4], nA[4], mA4[4], nB[4], mB4[4];
            ldfrag(hb, qc, r0A, r1A, aA, lA);
            ldfrag(hb, qc, r0B, r1B, aB, lB);
#pragma unroll 4
            for (int kc = 0; kc < 16; kc++) {
                if (kc < 15) {
                    ldfrag(hb, qc + 8 * (kc + 1), r0A, r1A, nA, mA4);
                    ldfrag(hb, qc + 8 * (kc + 1), r0B, r1B, nB, mB4);
                }
#pragma unroll
                for (int T = 0; T < 8; T++) {
                    size_t o = (size_t)((T * 16 + kc) * 32 + lane) * 2;
                    uint2 bh = *(const uint2*)(sBo + o);
                    uint2 bl = *(const uint2*)(sBo + 8192 + o);
                    mma4(oA + 4 * T, aA, bh.x, bh.y);
                    mma4(oA + 4 * T, aA, bl.x, bl.y);
                    mma4(oA + 4 * T, lA, bh.x, bh.y);
                    mma4(oB + 4 * T, aB, bh.x, bh.y);
                    mma4(oB + 4 * T, aB, bl.x, bl.y);
                    mma4(oB + 4 * T, lB, bh.x, bh.y);
                }
#pragma unroll
                for (int q = 0; q < 4; q++) {
                    aA[q] = nA[q]; lA[q] = mA4[q]; aB[q] = nB[q]; lB[q] = mB4[q];
                }
            }
#pragma unroll
            for (int ot = 0; ot < 8; ot++) {
                int cl = 8 * ot + qc * 2;
                float b0 = bcs[cl], b1 = bcs[cl + 1];
                int col = 64 * j + cl;
                if (r0A < cnt) {
                    float* p = out + (size_t)samp[r0A] * OT + (size_t)col * Tn + (i - 1);
                    p[0] = sigf(oA[4 * ot] + b0); p[Tn] = sigf(oA[4 * ot + 1] + b1);
                }
                if (r1A < cnt) {
                    float* p = out + (size_t)samp[r1A] * OT + (size_t)col * Tn + (i - 1);
                    p[0] = sigf(oA[4 * ot + 2] + b0); p[Tn] = sigf(oA[4 * ot + 3] + b1);
                }
                if (r0B < cnt) {
                    float* p = out + (size_t)samp[r0B] * OT + (size_t)col * Tn + (i - 1);
                    p[0] = sigf(oB[4 * ot] + b0); p[Tn] = sigf(oB[4 * ot + 1] + b1);
                }
                if (r1B < cnt) {
                    float* p = out + (size_t)samp[r1B] * OT + (size_t)col * Tn + (i - 1);
                    p[0] = sigf(oB[4 * ot + 2] + b0); p[Tn] = sigf(oB[4 * ot + 3] + b1);
                }
            }
        }
        if (i < Tn) {
            __threadfence();
            __syncthreads();
            bt += 8;
            if (tid == 0) {
                atomicAdd(&g_bar[grp], 1);
                int v;
                do {
                    asm volatile("ld.global.acquire.gpu.b32 %0,[%1];" : "=r"(v) : "l"(&g_bar[grp]) : "memory");
                } while (v < bt);
            }
            __syncthreads();
        }
    }
}

// ---------------------------------------------------------------------------
extern "C" void kernel_launch(void* const* d_in, const int* in_sizes, int n_in,
                              void* d_out, int out_size) {
    const float* x    = (const float*)d_in[0];
    const int*   cam  = (const int*)  d_in[1];
    const float* W_ih = (const float*)d_in[2];
    const float* W_hh = (const float*)d_in[3];
    const float* b_ih = (const float*)d_in[4];
    const float* b_hh = (const float*)d_in[5];
    const float* Wc   = (const float*)d_in[6];
    const float* bc   = (const float*)d_in[7];
    float* out = (float*)d_out;
    const int smem = 41184 * 4;
    cudaFuncSetAttribute(gru, cudaFuncAttributeMaxDynamicSharedMemorySize, smem);
    prep<<<1024, 256>>>(cam, W_ih, W_hh, Wc);
    gru<<<MAXG * 8, 384, smem>>>(x, b_ih, b_hh, bc, out);
}

// round 13
// speedup vs baseline: 1.2883x; 1.2883x over previous
#include <cuda_runtime.h>
#include <cuda_bf16.h>
#include <cstdint>

#define Bn 1024
#define Hn 256
#define Gn 768
#define On 512
#define Tn 60
#define Cc 15
#define MAXG 18
#define OT (On*Tn)

// B fragments as uint4 (bh0,bh1,bl0,bl1), fragment-ordered
__device__ __align__(16) uint4 g_Bw[120 * 6144];   // gate: 12T x 16kc x 32lane
__device__ __align__(16) uint4 g_Bo[120 * 4096];   // out:   8T x 16kc x 32lane
__device__ __align__(16) uint4 g_Bx[120 * 6144];   // Wi
__device__ __align__(16) uint32_t g_h[2 * MAXG * 2 * 16384];
__device__ int g_perm[Bn], g_gcam[MAXG], g_goff[MAXG], g_gcnt[MAXG], g_ngrp, g_bar[MAXG];

__device__ __forceinline__ float sigf(float v) { return 1.f / (1.f + __expf(-v)); }
__device__ __forceinline__ float tanhf_(float v) { return 2.f * sigf(2.f * v) - 1.f; }
__device__ __forceinline__ void bfsplit2(float f0, float f1, uint32_t& hi, uint32_t& lo) {
    unsigned short a = __bfloat16_as_ushort(__float2bfloat16_rn(f0));
    unsigned short b = __bfloat16_as_ushort(__float2bfloat16_rn(f1));
    float r0 = f0 - __uint_as_float((uint32_t)a << 16);
    float r1 = f1 - __uint_as_float((uint32_t)b << 16);
    unsigned short c = __bfloat16_as_ushort(__float2bfloat16_rn(r0));
    unsigned short d = __bfloat16_as_ushort(__float2bfloat16_rn(r1));
    hi = (uint32_t)a | ((uint32_t)b << 16);
    lo = (uint32_t)c | ((uint32_t)d << 16);
}
__device__ __forceinline__ void mma4(float* c, const uint32_t* a, uint32_t b0, uint32_t b1) {
    asm volatile("mma.sync.aligned.m16n8k16.row.col.f32.bf16.bf16.f32 "
                 "{%0,%1,%2,%3},{%4,%5,%6,%7},{%8,%9},{%0,%1,%2,%3};"
                 : "+f"(c[0]), "+f"(c[1]), "+f"(c[2]), "+f"(c[3])
                 : "r"(a[0]), "r"(a[1]), "r"(a[2]), "r"(a[3]), "r"(b0), "r"(b1));
}
__device__ __forceinline__ void ldfrag(const uint32_t* hb, int w0, int r0, int r1,
                                       uint32_t* ah, uint32_t* al) {
    ah[0] = hb[r0 * 128 + w0];             ah[1] = hb[r1 * 128 + w0];
    ah[2] = hb[r0 * 128 + w0 + 4];         ah[3] = hb[r1 * 128 + w0 + 4];
    al[0] = hb[16384 + r0 * 128 + w0];     al[1] = hb[16384 + r1 * 128 + w0];
    al[2] = hb[16384 + r0 * 128 + w0 + 4]; al[3] = hb[16384 + r1 * 128 + w0 + 4];
}

// ---------------------------------------------------------------------------
__global__ void prep(const int* __restrict__ cam, const float* __restrict__ Wi,
                     const float* __restrict__ Wh, const float* __restrict__ Wc) {
    if (blockIdx.x == 0) {
        __shared__ int cn[Cc], cu[Cc], co[Cc];
        int tid = threadIdx.x;
        if (tid < Cc) cn[tid] = 0;
        if (tid < MAXG) g_bar[tid] = 0;
        __syncthreads();
        for (int b = tid; b < Bn; b += blockDim.x) atomicAdd(&cn[cam[b]], 1);
        __syncthreads();
        if (tid == 0) {
            int o = 0;
            for (int c = 0; c < Cc; c++) { co[c] = o; cu[c] = o; o += cn[c]; }
            int g = 0;
            for (int c = 0; c < Cc; c++)
                for (int s = 0; s < cn[c] && g < MAXG; s += 128) {
                    g_gcam[g] = c; g_goff[g] = co[c] + s; g_gcnt[g] = min(128, cn[c] - s); g++;
                }
            g_ngrp = g;
        }
        __syncthreads();
        for (int b = tid; b < Bn; b += blockDim.x) { int p = atomicAdd(&cu[cam[b]], 1); g_perm[p] = b; }
    }
    int idx = blockIdx.x * blockDim.x + threadIdx.x, st = gridDim.x * blockDim.x;
    const int NWG = 120 * 12 * 512;
    for (int i = idx; i < NWG; i += st) {
        int lane = i & 31, kc = (i >> 5) & 15, T = (i >> 9) % 12, tile = i / (512 * 12);
        int c = tile >> 3, j = tile & 7;
        size_t row = (size_t)c * Gn + (T >> 2) * 256 + 32 * j + 8 * (T & 3) + (lane >> 2);
        int k0 = 16 * kc + (lane & 3) * 2;
        size_t o = (size_t)tile * 6144 + (T * 16 + kc) * 32 + lane;
        uint32_t h0, l0, h1, l1;
        const float* w = Wh + row * Hn;
        bfsplit2(w[k0], w[k0 + 1], h0, l0); bfsplit2(w[k0 + 8], w[k0 + 9], h1, l1);
        g_Bw[o] = make_uint4(h0, h1, l0, l1);
        w = Wi + row * Hn;
        bfsplit2(w[k0], w[k0 + 1], h0, l0); bfsplit2(w[k0 + 8], w[k0 + 9], h1, l1);
        g_Bx[o] = make_uint4(h0, h1, l0, l1);
    }
    const int NWO = 120 * 8 * 512;
    for (int i = idx; i < NWO; i += st) {
        int lane = i & 31, kc = (i >> 5) & 15, T = (i >> 9) & 7, tile = i / (512 * 8);
        int c = tile >> 3, j = tile & 7;
        const float* w = Wc + ((size_t)c * On + 64 * j + 8 * T + (lane >> 2)) * Hn;
        int k0 = 16 * kc + (lane & 3) * 2;
        uint32_t h0, l0, h1, l1;
        bfsplit2(w[k0], w[k0 + 1], h0, l0); bfsplit2(w[k0 + 8], w[k0 + 9], h1, l1);
        g_Bo[(size_t)tile * 4096 + (T * 16 + kc) * 32 + lane] = make_uint4(h0, h1, l0, l1);
    }
}

// ---------------------------------------------------------------------------
// 144 CTAs x 256 threads. Warp w handles M-tile w for BOTH the gate GEMM
// (step i) and the out GEMM (step i-1), sharing h A-fragments.
// smem: 6144+4096 uint4 = 163840 B, then bcs(64f)+bhs(32f)+samp(128i) = 896 B.
// ---------------------------------------------------------------------------
__global__ void __launch_bounds__(256, 1)
gru(const float* __restrict__ x, const float* __restrict__ b_ih,
    const float* __restrict__ b_hh, const float* __restrict__ bc,
    float* __restrict__ out) {
    extern __shared__ __align__(16) uint4 sm4[];
    uint4* sB  = sm4;                        // 6144 uint4 (gate)
    uint4* sBo = sm4 + 6144;                 // 4096 uint4 (out)
    float* bcs = (float*)(sm4 + 10240);      // 64
    float* bhs = bcs + 64;                   // 32
    int* samp  = (int*)(bhs + 32);           // 128

    const int grp = blockIdx.x >> 3, j = blockIdx.x & 7;
    if (grp >= g_ngrp) return;
    const int cam = g_gcam[grp], off = g_goff[grp], cnt = g_gcnt[grp];
    const int tile = cam * 8 + j;
    const int tid = threadIdx.x, wid = tid >> 5, lane = tid & 31;
    const int qr = lane >> 2, qc = lane & 3;
    const bool act = (16 * wid) < cnt;
    const int r0 = 16 * wid + qr, r1 = r0 + 8;

    if (tid < 128) samp[tid] = (tid < cnt) ? g_perm[off + tid] : 0;
    if (tid < 64) bcs[tid] = bc[cam * On + 64 * j + tid];
    if (tid < 32) bhs[tid] = b_hh[cam * Gn + 512 + 32 * j + tid];
    {
        const uint4* s = g_Bw + (size_t)tile * 6144;
        for (int i = tid; i < 6144; i += 256) sB[i] = s[i];
        const uint4* s2 = g_Bo + (size_t)tile * 4096;
        for (int i = tid; i < 4096; i += 256) sBo[i] = s2[i];
    }
    __syncthreads();

    float gi[48], hold[16];
    if (act) {  // gi = x@Wi + biases -> registers (pass-split too)
#pragma unroll
        for (int q = 0; q < 48; q++) gi[q] = 0.f;
        const uint4* bx = g_Bx + (size_t)tile * 6144;
        const float* x0 = (r0 < cnt) ? x + (size_t)samp[r0] * Hn : 0;
        const float* x1 = (r1 < cnt) ? x + (size_t)samp[r1] * Hn : 0;
        for (int kc = 0; kc < 16; kc++) {
            int k0 = 16 * kc + qc * 2;
            float2 p00 = x0 ? *(const float2*)(x0 + k0) : make_float2(0.f, 0.f);
            float2 p02 = x0 ? *(const float2*)(x0 + k0 + 8) : make_float2(0.f, 0.f);
            float2 p10 = x1 ? *(const float2*)(x1 + k0) : make_float2(0.f, 0.f);
            float2 p12 = x1 ? *(const float2*)(x1 + k0 + 8) : make_float2(0.f, 0.f);
            uint32_t ah[4], al[4];
            bfsplit2(p00.x, p00.y, ah[0], al[0]);
            bfsplit2(p10.x, p10.y, ah[1], al[1]);
            bfsplit2(p02.x, p02.y, ah[2], al[2]);
            bfsplit2(p12.x, p12.y, ah[3], al[3]);
            uint4 bg[12];
#pragma unroll
            for (int T = 0; T < 12; T++) bg[T] = bx[(T * 16 + kc) * 32 + lane];
#pragma unroll
            for (int T = 0; T < 12; T++) mma4(gi + 4 * T, ah, bg[T].x, bg[T].y);
#pragma unroll
            for (int T = 0; T < 12; T++) mma4(gi + 4 * T, ah, bg[T].z, bg[T].w);
#pragma unroll
            for (int T = 0; T < 12; T++) mma4(gi + 4 * T, al, bg[T].x, bg[T].y);
        }
#pragma unroll
        for (int T = 0; T < 12; T++) {
            int g = T >> 2;
            int col = g * 256 + 32 * j + 8 * (T & 3) + qc * 2;
            float b0 = b_ih[cam * Gn + col], b1 = b_ih[cam * Gn + col + 1];
            if (g < 2) { b0 += b_hh[cam * Gn + col]; b1 += b_hh[cam * Gn + col + 1]; }
            gi[4 * T] += b0; gi[4 * T + 1] += b1; gi[4 * T + 2] += b0; gi[4 * T + 3] += b1;
        }
    }
#pragma unroll
    for (int q = 0; q < 16; q++) hold[q] = 0.f;
    int bt = 0;

    for (int i = 0; i <= Tn; i++) {
        float gacc[48], oacc[32];
        if (act) {
#pragma unroll
            for (int q = 0; q < 48; q++) gacc[q] = 0.f;
#pragma unroll
            for (int q = 0; q < 32; q++) oacc[q] = 0.f;
            if (i > 0) {
                const uint32_t* hb = g_h + (size_t)((i & 1) * MAXG + grp) * 2 * 16384;
                const bool dog = i < Tn;
                uint32_t ah[4], al[4], nh[4], nl[4];
                ldfrag(hb, qc, r0, r1, ah, al);
                for (int kc = 0; kc < 16; kc++) {
                    if (kc < 15) ldfrag(hb, qc + 8 * (kc + 1), r0, r1, nh, nl);
                    uint4 bo[8];
#pragma unroll
                    for (int T = 0; T < 8; T++) bo[T] = sBo[(T * 16 + kc) * 32 + lane];
                    if (dog) {
                        uint4 bg[12];
#pragma unroll
                        for (int T = 0; T < 12; T++) bg[T] = sB[(T * 16 + kc) * 32 + lane];
                        // pass 1: a_hi * b_hi
#pragma unroll
                        for (int T = 0; T < 12; T++) mma4(gacc + 4 * T, ah, bg[T].x, bg[T].y);
#pragma unroll
                        for (int T = 0; T < 8; T++)  mma4(oacc + 4 * T, ah, bo[T].x, bo[T].y);
                        // pass 2: a_hi * b_lo
#pragma unroll
                        for (int T = 0; T < 12; T++) mma4(gacc + 4 * T, ah, bg[T].z, bg[T].w);
#pragma unroll
                        for (int T = 0; T < 8; T++)  mma4(oacc + 4 * T, ah, bo[T].z, bo[T].w);
                        // pass 3: a_lo * b_hi
#pragma unroll
                        for (int T = 0; T < 12; T++) mma4(gacc + 4 * T, al, bg[T].x, bg[T].y);
#pragma unroll
                        for (int T = 0; T < 8; T++)  mma4(oacc + 4 * T, al, bo[T].x, bo[T].y);
                    } else {
#pragma unroll
                        for (int T = 0; T < 8; T++)  mma4(oacc + 4 * T, ah, bo[T].x, bo[T].y);
#pragma unroll
                        for (int T = 0; T < 8; T++)  mma4(oacc + 4 * T, ah, bo[T].z, bo[T].w);
#pragma unroll
                        for (int T = 0; T < 8; T++)  mma4(oacc + 4 * T, al, bo[T].x, bo[T].y);
                    }
#pragma unroll
                    for (int q = 0; q < 4; q++) { ah[q] = nh[q]; al[q] = nl[q]; }
                }
            }
            if (i < Tn) {  // gate epilogue -> h_{i+1}
                uint32_t* dh = g_h + (size_t)(((i + 1) & 1) * MAXG + grp) * 2 * 16384;
#pragma unroll
                for (int tt = 0; tt < 4; tt++) {
                    int cb = 8 * tt + qc * 2;
                    float bn0 = bhs[cb], bn1 = bhs[cb + 1];
                    float h0, h1, h2, h3;
                    { float r = sigf(gi[4 * tt] + gacc[4 * tt]);
                      float z = sigf(gi[16 + 4 * tt] + gacc[16 + 4 * tt]);
                      float n = tanhf_(gi[32 + 4 * tt] + r * (gacc[32 + 4 * tt] + bn0));
                      h0 = (1.f - z) * n + z * hold[4 * tt]; hold[4 * tt] = h0; }
                    { float r = sigf(gi[4 * tt + 1] + gacc[4 * tt + 1]);
                      float z = sigf(gi[16 + 4 * tt + 1] + gacc[16 + 4 * tt + 1]);
                      float n = tanhf_(gi[32 + 4 * tt + 1] + r * (gacc[32 + 4 * tt + 1] + bn1));
                      h1 = (1.f - z) * n + z * hold[4 * tt + 1]; hold[4 * tt + 1] = h1; }
                    { float r = sigf(gi[4 * tt + 2] + gacc[4 * tt + 2]);
                      float z = sigf(gi[16 + 4 * tt + 2] + gacc[16 + 4 * tt + 2]);
                      float n = tanhf_(gi[32 + 4 * tt + 2] + r * (gacc[32 + 4 * tt + 2] + bn0));
                      h2 = (1.f - z) * n + z * hold[4 * tt + 2]; hold[4 * tt + 2] = h2; }
                    { float r = sigf(gi[4 * tt + 3] + gacc[4 * tt + 3]);
                      float z = sigf(gi[16 + 4 * tt + 3] + gacc[16 + 4 * tt + 3]);
                      float n = tanhf_(gi[32 + 4 * tt + 3] + r * (gacc[32 + 4 * tt + 3] + bn1));
                      h3 = (1.f - z) * n + z * hold[4 * tt + 3]; hold[4 * tt + 3] = h3; }
                    uint32_t w0h, w0l, w1h, w1l;
                    bfsplit2(h0, h1, w0h, w0l);
                    bfsplit2(h2, h3, w1h, w1l);
                    int wrd = 16 * j + 4 * tt + qc;
                    dh[r0 * 128 + wrd] = w0h; dh[r1 * 128 + wrd] = w1h;
                    dh[16384 + r0 * 128 + wrd] = w0l; dh[16384 + r1 * 128 + wrd] = w1l;
                }
            }
            if (i > 0) {  // out epilogue: t = i-1
#pragma unroll
                for (int ot = 0; ot < 8; ot++) {
                    int cl = 8 * ot + qc * 2;
                    float b0 = bcs[cl], b1 = bcs[cl + 1];
                    int col = 64 * j + cl;
                    if (r0 < cnt) {
                        float* p = out + (size_t)samp[r0] * OT + (size_t)col * Tn + (i - 1);
                        p[0] = sigf(oacc[4 * ot] + b0); p[Tn] = sigf(oacc[4 * ot + 1] + b1);
                    }
                    if (r1 < cnt) {
                        float* p = out + (size_t)samp[r1] * OT + (size_t)col * Tn + (i - 1);
                        p[0] = sigf(oacc[4 * ot + 2] + b0); p[Tn] = sigf(oacc[4 * ot + 3] + b1);
                    }
                }
            }
        }
        if (i < Tn) {
            __threadfence();
            __syncthreads();
            bt += 8;
            if (tid == 0) {
                atomicAdd(&g_bar[grp], 1);
                int v;
                do {
                    asm volatile("ld.global.acquire.gpu.b32 %0,[%1];" : "=r"(v) : "l"(&g_bar[grp]) : "memory");
                } while (v < bt);
            }
            __syncthreads();
        }
    }
}

// ---------------------------------------------------------------------------
extern "C" void kernel_launch(void* const* d_in, const int* in_sizes, int n_in,
                              void* d_out, int out_size) {
    const float* x    = (const float*)d_in[0];
    const int*   cam  = (const int*)  d_in[1];
    const float* W_ih = (const float*)d_in[2];
    const float* W_hh = (const float*)d_in[3];
    const float* b_ih = (const float*)d_in[4];
    const float* b_hh = (const float*)d_in[5];
    const float* Wc   = (const float*)d_in[6];
    const float* bc   = (const float*)d_in[7];
    float* out = (float*)d_out;
    // 10240 uint4 (163840 B) + 64f + 32f + 128i (896 B) = 164736, padded
    const int smem = 165120;
    cudaFuncSetAttribute(gru, cudaFuncAttributeMaxDynamicSharedMemorySize, smem);
    prep<<<1024, 256>>>(cam, W_ih, W_hh, Wc);
    gru<<<MAXG * 8, 256, smem>>>(x, b_ih, b_hh, bc, out);
}